// round 16
// baseline (speedup 1.0000x reference)
#include <cuda_runtime.h>
#include <cstdint>

#define NCTA   64
#define TPB    384      // 8 compute warps + 4 poller warps
#define HDIM   512
#define TSTEPS 512
#define NREP   8        // packet replicas (one per group of 8 consumer CTAs)
#define NSLOT  4        // ring depth over time steps (tags disambiguate)

typedef unsigned long long ull;

// Ring buffer: g_pk[slot][r][p] — slot = t mod 4. One 128B line per (slot,r,p);
// 8 packets packed in the first 64B (ull slot w = producer warp w).
// packet: lo32 = tag (epoch<<10 | t), hi32 = float bits of mem value.
// 256KB -> L2-resident (R12 sweet spot).
__device__ __align__(128) ull g_pk[NSLOT][NREP][NCTA][16];
__device__ float g_acc[HDIM];
__device__ unsigned int g_epoch[NCTA];
__device__ unsigned int g_done;

#define SLOT_STRIDE (NREP * NCTA * 16)   // ull elements per ring slot

__device__ __forceinline__ void ld_pk2(const ull* p, ull& x, ull& y) {
    asm volatile("ld.relaxed.gpu.v2.u64 {%0, %1}, [%2];" : "=l"(x), "=l"(y) : "l"(p));
}
__device__ __forceinline__ void st_pk(ull* p, ull v) {
    asm volatile("st.relaxed.gpu.b64 [%0], %1;" :: "l"(p), "l"(v));
}
__device__ __forceinline__ float ld_rel_f(const float* p) {
    float v;
    asm volatile("ld.relaxed.gpu.f32 %0, [%1];" : "=f"(v) : "l"(p));
    return v;
}
__device__ __forceinline__ void st_rel_f(float* p, float v) {
    asm volatile("st.relaxed.gpu.f32 [%0], %1;" :: "l"(p), "f"(v));
}
__device__ __forceinline__ void fma2(ull& d, ull a, ull b) {
    asm("fma.rn.f32x2 %0, %1, %2, %0;" : "+l"(d) : "l"(a), "l"(b));
}
__device__ __forceinline__ ull packf2(float lo, float hi) {
    ull r;
    asm("mov.b64 %0, {%1, %2};" : "=l"(r) : "f"(lo), "f"(hi));
    return r;
}
__device__ __forceinline__ float2 unpackf2(ull v) {
    float lo, hi;
    asm("mov.b64 {%0, %1}, %2;" : "=f"(lo), "=f"(hi) : "l"(v));
    return make_float2(lo, hi);
}
__device__ __forceinline__ void bar_named(int id, int cnt) {
    asm volatile("bar.sync %0, %1;" :: "r"(id), "r"(cnt) : "memory");
}
// fast sigmoid / tanh via MUFU ex2 + rcp (err ~1e-7, no branches)
__device__ __forceinline__ float fsig(float x) {
    float e, r;
    asm("ex2.approx.f32 %0, %1;" : "=f"(e) : "f"(-1.4426950408889634f * x));
    asm("rcp.approx.f32 %0, %1;" : "=f"(r) : "f"(1.0f + e));
    return r;
}
__device__ __forceinline__ float ftanh(float x) {
    float e, r;
    asm("ex2.approx.f32 %0, %1;" : "=f"(e) : "f"(2.8853900817779268f * x)); // e^{2x}
    asm("rcp.approx.f32 %0, %1;" : "=f"(r) : "f"(1.0f + e));
    return fmaf(-2.0f, r, 1.0f);
}

__global__ void __launch_bounds__(TPB, 1)
slstm_kernel(const float* __restrict__ W_hh2, const float* __restrict__ b_ih2,
             const float* __restrict__ b_hh2, const float* __restrict__ thr2p,
             const float* __restrict__ W_fc,  const float* __restrict__ b_fc,
             float* __restrict__ out)
{
    __shared__ __align__(16) float hstage[2][8][64];   // [parity][comp-warp][64 h]
    __shared__ float partial[2][8 * 33 + 8];           // [parity][u*33 + g*8 + s]
    __shared__ float yout[8];
    __shared__ unsigned int s_epoch;
    __shared__ int s_win;

    const int bid  = blockIdx.x;
    const int tid  = threadIdx.x;
    const int w    = tid >> 5;
    const int lane = tid & 31;
    const bool isComp = (w < 8);

    if (tid == 0) s_epoch = atomicAdd(&g_epoch[bid], 1u) + 1u;

    // ---- compute-warp setup ----
    ull wreg[32];
    float cbias = 0.f, thr = 0.f;
    int gb = 0, ub = 0, gc = 0;
    if (isComp) {
        gb = lane >> 3;  ub = lane & 7;  gc = gb;
        const int rowb = gb * HDIM + bid * 8 + ub;
        const float4* wp = (const float4*)(W_hh2 + (size_t)rowb * HDIM + w * 64);
#pragma unroll
        for (int m = 0; m < 16; m++) {
            float4 v = wp[m];
            wreg[2 * m]     = packf2(v.x, v.y);
            wreg[2 * m + 1] = packf2(v.z, v.w);
        }
        const int rowc = gc * HDIM + bid * 8 + w;
        cbias = b_ih2[rowc] + b_hh2[rowc];
        thr   = *thr2p;
    }
    __syncthreads();
    const unsigned int tagbase = s_epoch << 10;

    if (!isComp) {
        // ================= POLLER WARPS (w = 8..11) =================
        // Poller pw stages mem vectors for compute warps {2pw, 2pw+1}.
        // lane -> cw = 2pw + (lane>>4); l4 = lane&15: line = 8cw + (l4>>1),
        // packets (l4&1)*4 .. +3  (two v2.u64 polls on one private line).
        const int pw = w - 8;
        const int cw = 2 * pw + (lane >> 4);
        const int l4 = lane & 15;
        const int lineLocal = l4 >> 1;
        const int half = l4 & 1;
        const int rb = bid >> 3;
        const ull* base = &g_pk[0][rb][8 * cw + lineLocal][half * 4];
        const int si = lineLocal * 8 + half * 4;
        const int barid = 1 + pw;

        for (int t = 1; t <= TSTEPS - 1; t++) {
            const unsigned int want = tagbase + (unsigned int)t;
            const ull* q = base + (((unsigned)t & 3u) * SLOT_STRIDE);
            ull a0, a1, b0, b1;
            bool d0 = false, d1 = false;
            do {
                if (!d0) { ld_pk2(q,     a0, a1); d0 = ((unsigned)a0 == want) & ((unsigned)a1 == want); }
                if (!d1) { ld_pk2(q + 2, b0, b1); d1 = ((unsigned)b0 == want) & ((unsigned)b1 == want); }
            } while (!(d0 && d1));
            float4 val = make_float4(
                __uint_as_float((unsigned)(a0 >> 32)), __uint_as_float((unsigned)(a1 >> 32)),
                __uint_as_float((unsigned)(b0 >> 32)), __uint_as_float((unsigned)(b1 >> 32)));
            *(float4*)&hstage[t & 1][cw][si] = val;
            bar_named(barid, 96);   // handoff to the 2 compute warps (orders STS)
        }
    } else {
        // ================= COMPUTE WARPS (w = 0..7) =================
        float cst = 0.f, memv = 0.f, accv = 0.f;
        float wt = expf(-0.05f * (float)(TSTEPS - 1));
        const float estep = expf(0.05f);
        ull* ppub_base = &g_pk[0][lane & 7][bid][w];   // lanes 0..7 publish replicas
        const int barp = 1 + (w >> 1);

        for (int t = 1; t <= TSTEPS; t++) {
            if (t > 1) {
                // ---- A: wait for poller handoff of mem_{t-1} ----
                bar_named(barp, 96);

                // ---- B: partial dot, row (gb,unit ub) over K in [64w, 64w+64) ----
                ull acc0 = 0ull, acc1 = 0ull;
                const float4* hb = (const float4*)hstage[(t - 1) & 1][w];
#pragma unroll
                for (int q = 0; q < 16; q++) {
                    float4 hv = hb[q];               // broadcast LDS.128
                    fma2(acc0, wreg[2 * q],     packf2(hv.x, hv.y));
                    fma2(acc1, wreg[2 * q + 1], packf2(hv.z, hv.w));
                }
                float2 f0 = unpackf2(acc0), f1 = unpackf2(acc1);
                partial[t & 1][ub * 33 + gb * 8 + w] = (f0.x + f0.y) + (f1.x + f1.y);
                bar_named(8, 256);                   // compute-warp barrier
            }

            // ---- C: warp w = unit bid*8+w; flat 8-scalar broadcast LDS reduce ----
            float v;
            if (t > 1) {
                const float* pp = &partial[t & 1][w * 33 + gc * 8];
                float p0 = pp[0], p1 = pp[1], p2 = pp[2], p3 = pp[3];
                float p4 = pp[4], p5 = pp[5], p6 = pp[6], p7 = pp[7];
                v = ((p0 + p1) + (p2 + p3)) + ((p4 + p5) + (p6 + p7));
            } else {
                v = 0.f;   // mem_0 = 0 -> gates = bias only
            }

            float x = v + cbias;
            float a  = (gc == 2) ? ftanh(x) : fsig(x);
            float e1 = __shfl_xor_sync(0xffffffffu, a, 8);
            float e2 = __shfl_xor_sync(0xffffffffu, a, 16);
            float e3 = __shfl_xor_sync(0xffffffffu, a, 24);
            auto pick = [&](int j) -> float {
                int m = gc ^ j;
                return (m & 2) ? ((m & 1) ? e3 : e2) : ((m & 1) ? e1 : a);
            };
            float i_ = pick(0), f_ = pick(1), g_ = pick(2), o_ = pick(3);
            float rst = (memv > thr) ? thr : 0.f;   // PREVIOUS mem (matches reference)
            cst  = fmaf(f_, cst, i_ * g_);
            memv = fmaf(o_, ftanh(cst), -rst);
            // ---- publish all 8 replicas in parallel (memv is warp-uniform) ----
            if (lane < 8) {
                ull* ppub = ppub_base + (((unsigned)t & 3u) * SLOT_STRIDE);
                st_pk(ppub, ((ull)__float_as_uint(memv) << 32) | (ull)(tagbase + (unsigned int)t));
            }
            accv = fmaf(wt, memv, accv);            // off the publish path
            wt *= estep;
        }
        if (lane == 0) st_rel_f(&g_acc[bid * 8 + w], accv);
    }

    __syncthreads();
    if (tid == 0) {
        __threadfence();
        unsigned int r = atomicAdd(&g_done, 1u);
        s_win = ((r & (NCTA - 1)) == (NCTA - 1));
    }
    __syncthreads();

    // ---- fused FC epilogue: last CTA computes [8] outputs, broadcasts to [256,8] ----
    if (s_win) {
        __threadfence();
        if (w < 8) {
            float sum = 0.f;
#pragma unroll
            for (int m = 0; m < 16; m++) {
                int k = m * 32 + lane;
                sum += ld_rel_f(&g_acc[k]) * W_fc[w * HDIM + k];
            }
#pragma unroll
            for (int o = 16; o; o >>= 1) sum += __shfl_xor_sync(0xffffffffu, sum, o);
            if (lane == 0) {
                double rr = exp(-0.05);
                double Z  = (1.0 - exp(-0.05 * (double)TSTEPS)) / (1.0 - rr);
                yout[w] = (float)((double)sum / Z) + b_fc[w];
            }
        }
        __syncthreads();
        for (int i = tid; i < 256 * 8; i += TPB) out[i] = yout[i & 7];
    }
}

extern "C" void kernel_launch(void* const* d_in, const int* in_sizes, int n_in,
                              void* d_out, int out_size)
{
    // inputs: 0 x, 1 W_ih1, 2 W_hh1, 3 b_ih1, 4 b_hh1, 5 thr1,
    //         6 W_ih2, 7 W_hh2, 8 b_ih2, 9 b_hh2, 10 thr2, 11 W_fc, 12 b_fc
    const float* W_hh2 = (const float*)d_in[7];
    const float* b_ih2 = (const float*)d_in[8];
    const float* b_hh2 = (const float*)d_in[9];
    const float* thr2  = (const float*)d_in[10];
    const float* W_fc  = (const float*)d_in[11];
    const float* b_fc  = (const float*)d_in[12];

    slstm_kernel<<<NCTA, TPB>>>(W_hh2, b_ih2, b_hh2, thr2, W_fc, b_fc, (float*)d_out);
}

// round 17
// speedup vs baseline: 1.3515x; 1.3515x over previous
#include <cuda_runtime.h>
#include <cstdint>

#define NCTA   64
#define TPB    256
#define HDIM   512
#define TSTEPS 512
#define NREP   8        // packet replicas (one per group of 8 consumer CTAs)
#define NSLOT  4        // ring depth over time steps (tags disambiguate)

typedef unsigned long long ull;

// Ring buffer: g_pk[slot][r][p] — slot = t mod 4. One 128B line per (slot,r,p);
// 8 packets packed in the first 64B (ull slot w = producer warp w).
// packet: lo32 = tag (epoch<<10 | t), hi32 = float bits of mem value.
// 256KB total -> L2-resident; pollers per line = 32 (R12 sweet spot).
__device__ __align__(128) ull g_pk[NSLOT][NREP][NCTA][16];
__device__ float g_acc[HDIM];
__device__ unsigned int g_epoch[NCTA];
__device__ unsigned int g_done;

#define SLOT_STRIDE (NREP * NCTA * 16)   // ull elements per ring slot (8192)

__device__ __forceinline__ void ld_pk2(const ull* p, ull& x, ull& y) {
    asm volatile("ld.relaxed.gpu.v2.u64 {%0, %1}, [%2];" : "=l"(x), "=l"(y) : "l"(p));
}
__device__ __forceinline__ void st_pk(ull* p, ull v) {
    asm volatile("st.relaxed.gpu.b64 [%0], %1;" :: "l"(p), "l"(v));
}
__device__ __forceinline__ float ld_rel_f(const float* p) {
    float v;
    asm volatile("ld.relaxed.gpu.f32 %0, [%1];" : "=f"(v) : "l"(p));
    return v;
}
__device__ __forceinline__ void st_rel_f(float* p, float v) {
    asm volatile("st.relaxed.gpu.f32 [%0], %1;" :: "l"(p), "f"(v));
}
__device__ __forceinline__ void fma2(ull& d, ull a, ull b) {
    asm("fma.rn.f32x2 %0, %1, %2, %0;" : "+l"(d) : "l"(a), "l"(b));
}
__device__ __forceinline__ ull packf2(float lo, float hi) {
    ull r;
    asm("mov.b64 %0, {%1, %2};" : "=l"(r) : "f"(lo), "f"(hi));
    return r;
}
__device__ __forceinline__ float2 unpackf2(ull v) {
    float lo, hi;
    asm("mov.b64 {%0, %1}, %2;" : "=f"(lo), "=f"(hi) : "l"(v));
    return make_float2(lo, hi);
}
// fast sigmoid / tanh via MUFU ex2 + rcp (err ~1e-7, no branches)
__device__ __forceinline__ float fsig(float x) {
    float e, r;
    asm("ex2.approx.f32 %0, %1;" : "=f"(e) : "f"(-1.4426950408889634f * x));
    asm("rcp.approx.f32 %0, %1;" : "=f"(r) : "f"(1.0f + e));
    return r;
}
__device__ __forceinline__ float ftanh(float x) {
    float e, r;
    asm("ex2.approx.f32 %0, %1;" : "=f"(e) : "f"(2.8853900817779268f * x)); // e^{2x}
    asm("rcp.approx.f32 %0, %1;" : "=f"(r) : "f"(1.0f + e));
    return fmaf(-2.0f, r, 1.0f);
}

__global__ void __launch_bounds__(TPB, 1)
slstm_kernel(const float* __restrict__ W_hh2, const float* __restrict__ b_ih2,
             const float* __restrict__ b_hh2, const float* __restrict__ thr2p,
             const float* __restrict__ W_fc,  const float* __restrict__ b_fc,
             float* __restrict__ out)
{
    __shared__ __align__(16) float hstage[8][64];  // [seg-warp][64 staged h floats]
    __shared__ float partial[2][8 * 33 + 8];       // [parity][u*33 + g*8 + s]
    __shared__ float yout[8];
    __shared__ unsigned int s_epoch;
    __shared__ int s_win;

    const int bid  = blockIdx.x;
    const int tid  = threadIdx.x;
    const int w    = tid >> 5;       // warp = K segment (phase B) = unit (phase C)
    const int lane = tid & 31;

    if (tid == 0) s_epoch = atomicAdd(&g_epoch[bid], 1u) + 1u;

    // ---- phase-B identity: row = gate gb * 512 + unit (bid*8 + ub), K seg w ----
    const int gb   = lane >> 3;
    const int ub   = lane & 7;
    const int rowb = gb * HDIM + bid * 8 + ub;
    ull wreg[32];
    const float4* wp = (const float4*)(W_hh2 + (size_t)rowb * HDIM + w * 64);
#pragma unroll
    for (int m = 0; m < 16; m++) {
        float4 v = wp[m];
        wreg[2 * m]     = packf2(v.x, v.y);
        wreg[2 * m + 1] = packf2(v.z, v.w);
    }

    // ---- phase-C identity: warp w owns unit bid*8+w; lane = gc*8 + sc ----
    const int gc   = lane >> 3;
    const int rowc = gc * HDIM + bid * 8 + w;
    const float cbias = b_ih2[rowc] + b_hh2[rowc];
    const float thr   = *thr2p;
    __syncthreads();

    const unsigned int tagbase = s_epoch << 10;
    float cst = 0.f, memv = 0.f, accv = 0.f;
    float rst = 0.f;                  // hoisted reset: (mem_{t-1} > thr) ? thr : 0
    float wt = expf(-0.05f * (float)(TSTEPS - 1));
    const float estep = expf(0.05f);

    // ---- poll mapping (replica rb = bid>>3): warp w needs producer CTAs
    // [8w, 8w+8). lane covers line pc = 8w + (lane>>2), packets 2*(lane&3), +1. ----
    const int rb = bid >> 3;
    const ull* pk_base = &g_pk[0][rb][8 * w + (lane >> 2)][(lane & 3) * 2];
    const int i0 = (lane >> 2) * 8 + (lane & 3) * 2;   // staging index (even)
    // ---- publish: lanes 0..7 store the 8 replicas in parallel, slot = warp ----
    ull* ppub_base = &g_pk[0][lane & 7][bid][w];       // only lanes 0..7 store

    for (int t = 1; t <= TSTEPS; t++) {
        if (t > 1) {
            // ---- A: cold depth-1 v2 poll of ring slot (t-1) & 3 ----
            const unsigned int want = tagbase + (unsigned int)(t - 1);
            const ull* pk = pk_base + (((unsigned)(t - 1) & 3u) * SLOT_STRIDE);
            ull v0, v1;
            do {
                ld_pk2(pk, v0, v1);
            } while (((unsigned int)v0 != want) || ((unsigned int)v1 != want));
            *(float2*)&hstage[w][i0] =
                make_float2(__uint_as_float((unsigned int)(v0 >> 32)),
                            __uint_as_float((unsigned int)(v1 >> 32)));
            __syncwarp();

            // ---- B: partial dot, row rowb over K in [64w, 64w+64) ----
            ull acc0 = 0ull, acc1 = 0ull;
            const float4* hb = (const float4*)hstage[w];
#pragma unroll
            for (int q = 0; q < 16; q++) {
                float4 hv = hb[q];               // broadcast LDS.128
                fma2(acc0, wreg[2 * q],     packf2(hv.x, hv.y));
                fma2(acc1, wreg[2 * q + 1], packf2(hv.z, hv.w));
            }
            float2 f0 = unpackf2(acc0), f1 = unpackf2(acc1);
            partial[t & 1][ub * 33 + gb * 8 + w] = (f0.x + f0.y) + (f1.x + f1.y);
            __syncthreads();
        }

        // ---- C: warp w = unit bid*8+w; flat 8-scalar broadcast LDS reduce ----
        float v;
        if (t > 1) {
            const float* pp = &partial[t & 1][w * 33 + gc * 8];
            float p0 = pp[0], p1 = pp[1], p2 = pp[2], p3 = pp[3];
            float p4 = pp[4], p5 = pp[5], p6 = pp[6], p7 = pp[7];
            v = ((p0 + p1) + (p2 + p3)) + ((p4 + p5) + (p6 + p7));
        } else {
            v = 0.f;   // mem_0 = 0 -> gates = bias only
        }

        // ---- exchange RAW pre-activations first, then run all 4 MUFU
        // activation chains in parallel (they pipeline at rt=8) ----
        float x = v + cbias;                    // own gate's pre-activation
        float x1 = __shfl_xor_sync(0xffffffffu, x, 8);
        float x2 = __shfl_xor_sync(0xffffffffu, x, 16);
        float x3 = __shfl_xor_sync(0xffffffffu, x, 24);
        auto pickx = [&](int j) -> float {
            int m = gc ^ j;
            return (m & 2) ? ((m & 1) ? x3 : x2) : ((m & 1) ? x1 : x);
        };
        float xi = pickx(0), xf = pickx(1), xg = pickx(2), xo = pickx(3);
        float i_ = fsig(xi), f_ = fsig(xf), g_ = ftanh(xg), o_ = fsig(xo);
        cst  = fmaf(f_, cst, i_ * g_);
        memv = fmaf(o_, ftanh(cst), -rst);      // rst precomputed last step
        // ---- publish all 8 replicas in parallel (memv is warp-uniform) ----
        if (lane < 8) {
            ull* ppub = ppub_base + (((unsigned)t & 3u) * SLOT_STRIDE);
            st_pk(ppub, ((ull)__float_as_uint(memv) << 32) | (ull)(tagbase + (unsigned int)t));
        }
        rst  = (memv > thr) ? thr : 0.f;        // for NEXT step (off publish path)
        accv = fmaf(wt, memv, accv);            // off the publish path
        wt *= estep;
    }

    if (lane == 0) st_rel_f(&g_acc[bid * 8 + w], accv);
    __syncthreads();
    if (tid == 0) {
        __threadfence();
        unsigned int r = atomicAdd(&g_done, 1u);
        s_win = ((r & (NCTA - 1)) == (NCTA - 1));
    }
    __syncthreads();

    // ---- fused FC epilogue: last CTA computes [8] outputs, broadcasts to [256,8] ----
    if (s_win) {
        __threadfence();
        float sum = 0.f;
#pragma unroll
        for (int m = 0; m < 16; m++) {
            int k = m * 32 + lane;
            sum += ld_rel_f(&g_acc[k]) * W_fc[w * HDIM + k];
        }
#pragma unroll
        for (int o = 16; o; o >>= 1) sum += __shfl_xor_sync(0xffffffffu, sum, o);
        if (lane == 0) {
            double rr = exp(-0.05);
            double Z  = (1.0 - exp(-0.05 * (double)TSTEPS)) / (1.0 - rr);
            yout[w] = (float)((double)sum / Z) + b_fc[w];
        }
        __syncthreads();
        for (int i = tid; i < 256 * 8; i += TPB) out[i] = yout[i & 7];
    }
}

extern "C" void kernel_launch(void* const* d_in, const int* in_sizes, int n_in,
                              void* d_out, int out_size)
{
    // inputs: 0 x, 1 W_ih1, 2 W_hh1, 3 b_ih1, 4 b_hh1, 5 thr1,
    //         6 W_ih2, 7 W_hh2, 8 b_ih2, 9 b_hh2, 10 thr2, 11 W_fc, 12 b_fc
    const float* W_hh2 = (const float*)d_in[7];
    const float* b_ih2 = (const float*)d_in[8];
    const float* b_hh2 = (const float*)d_in[9];
    const float* thr2  = (const float*)d_in[10];
    const float* W_fc  = (const float*)d_in[11];
    const float* b_fc  = (const float*)d_in[12];

    slstm_kernel<<<NCTA, TPB>>>(W_hh2, b_ih2, b_hh2, thr2, W_fc, b_fc, (float*)d_out);
}